// round 3
// baseline (speedup 1.0000x reference)
#include <cuda_runtime.h>
#include <cstdint>

#define N_ROWS  2048
#define D_DIM   512
#define H_DIM   512
#define N_HEADS 16

#define BM 64
#define BN 64
#define BK 16
// 256 threads, 16x16 thread grid, each thread computes 4 rows x 4 cols

__device__ int g_perm[N_ROWS];
__device__ int g_off[N_HEADS + 1];

// ---------------------------------------------------------------------------
// Kernel 1: counting-sort rows by head (single block; N=2048 is tiny).
// Handles idx stored as int32 OR int64 (little-endian) — detected on device:
// for int64 values in [0,16), every odd 32-bit word is 0; for int32 random
// heads, some odd word in [0,2048) is nonzero with probability 1-16^-1024.
// ---------------------------------------------------------------------------
__global__ void bucket_kernel(const int* __restrict__ idxw) {
    __shared__ int cnt[N_HEADS];
    __shared__ int cur[N_HEADS];
    __shared__ int offs[N_HEADS + 1];
    __shared__ int odd_nonzero;
    int tid = threadIdx.x;
    if (tid < N_HEADS) cnt[tid] = 0;
    if (tid == 0) odd_nonzero = 0;
    __syncthreads();

    // dtype probe: scan odd words within the first 2048 words (valid for both)
    int local = 0;
    for (int i = tid; i < N_ROWS / 2; i += blockDim.x)
        if (idxw[2 * i + 1] != 0) local = 1;
    if (local) atomicOr(&odd_nonzero, 1);
    __syncthreads();
    const bool is64 = (odd_nonzero == 0);

    for (int i = tid; i < N_ROWS; i += blockDim.x) {
        int h = is64 ? idxw[2 * i] : idxw[i];
        atomicAdd(&cnt[h], 1);
    }
    __syncthreads();
    if (tid == 0) {
        int acc = 0;
        for (int h = 0; h < N_HEADS; h++) {
            offs[h] = acc;
            cur[h]  = acc;
            acc += cnt[h];
        }
        offs[N_HEADS] = acc;
    }
    __syncthreads();
    if (tid <= N_HEADS) g_off[tid] = offs[tid];
    for (int i = tid; i < N_ROWS; i += blockDim.x) {
        int h = is64 ? idxw[2 * i] : idxw[i];
        int p = atomicAdd(&cur[h], 1);
        g_perm[p] = i;
    }
}

// ---------------------------------------------------------------------------
// Packed f32x2 helpers (FFMA2 — 2x fp32 FMA throughput vs 3-reg FFMA)
// ---------------------------------------------------------------------------
__device__ __forceinline__ unsigned long long fma2(unsigned long long a,
                                                   unsigned long long b,
                                                   unsigned long long c) {
    unsigned long long d;
    asm("fma.rn.f32x2 %0, %1, %2, %3;" : "=l"(d) : "l"(a), "l"(b), "l"(c));
    return d;
}
__device__ __forceinline__ unsigned long long pack2(float lo, float hi) {
    unsigned long long r;
    asm("mov.b64 %0, {%1, %2};" : "=l"(r) : "f"(lo), "f"(hi));
    return r;
}
__device__ __forceinline__ float2 unpack2(unsigned long long v) {
    float2 r;
    asm("mov.b64 {%0, %1}, %2;" : "=f"(r.x), "=f"(r.y) : "l"(v));
    return r;
}

// ---------------------------------------------------------------------------
// Kernel 2: grouped GEMM. grid = (H/BN, N_HEADS, maxRowTiles).
// Block (h, nt, rt) computes out[perm[off[h]+rt*BM : ...], nt*BN : nt*BN+BN].
// ---------------------------------------------------------------------------
__global__ __launch_bounds__(256)
void multilinear_gemm(const float* __restrict__ X,
                      const float* __restrict__ W,
                      const float* __restrict__ B,
                      float* __restrict__ out) {
    const int h    = blockIdx.y;
    const int base = g_off[h];
    const int end  = g_off[h + 1];
    const int row0 = base + blockIdx.z * BM;
    if (row0 >= end) return;
    const int n0 = blockIdx.x * BN;

    __shared__ float As[BK][BM];   // transposed X tile
    __shared__ float Bs[BK][BN];   // W tile

    const int tid = threadIdx.x;
    const int tx  = tid & 15;      // col group (4 cols each)
    const int ty  = tid >> 4;      // row group (4 rows each)

    // global-load mapping (independent from compute mapping)
    const int lm  = tid & 63;        // As: row within tile
    const int lk  = (tid >> 6) * 4;  // As: k base (float4)
    const int bn4 = (tid & 15) * 4;  // Bs: n base (float4)
    const int bk  = tid >> 4;        // Bs: k row

    const float* Wh = W + (size_t)h * D_DIM * H_DIM;

    const int  mrow   = row0 + lm;
    const bool mvalid = (mrow < end);
    const int  gr     = mvalid ? g_perm[mrow] : 0;

    unsigned long long acc[4][2];
#pragma unroll
    for (int i = 0; i < 4; i++) { acc[i][0] = 0ull; acc[i][1] = 0ull; }

    for (int k0 = 0; k0 < D_DIM; k0 += BK) {
        float4 xa = make_float4(0.f, 0.f, 0.f, 0.f);
        if (mvalid)
            xa = *reinterpret_cast<const float4*>(X + (size_t)gr * D_DIM + k0 + lk);
        As[lk + 0][lm] = xa.x;
        As[lk + 1][lm] = xa.y;
        As[lk + 2][lm] = xa.z;
        As[lk + 3][lm] = xa.w;

        float4 wb = *reinterpret_cast<const float4*>(
            Wh + (size_t)(k0 + bk) * H_DIM + n0 + bn4);
        *reinterpret_cast<float4*>(&Bs[bk][bn4]) = wb;

        __syncthreads();

#pragma unroll
        for (int kk = 0; kk < BK; kk++) {
            unsigned long long ap[4], bp[2];
#pragma unroll
            for (int i = 0; i < 4; i++) {
                float a = As[kk][ty * 4 + i];
                ap[i] = pack2(a, a);
            }
            bp[0] = *reinterpret_cast<const unsigned long long*>(&Bs[kk][tx * 4]);
            bp[1] = *reinterpret_cast<const unsigned long long*>(&Bs[kk][tx * 4 + 2]);
#pragma unroll
            for (int i = 0; i < 4; i++) {
                acc[i][0] = fma2(ap[i], bp[0], acc[i][0]);
                acc[i][1] = fma2(ap[i], bp[1], acc[i][1]);
            }
        }
        __syncthreads();
    }

    // epilogue: add bias, scatter to original row positions
    const int n = n0 + tx * 4;
    const float4 bias = *reinterpret_cast<const float4*>(B + (size_t)h * H_DIM + n);
#pragma unroll
    for (int i = 0; i < 4; i++) {
        int r = row0 + ty * 4 + i;
        if (r < end) {
            int orow = g_perm[r];
            float2 c0 = unpack2(acc[i][0]);
            float2 c1 = unpack2(acc[i][1]);
            float4 v  = make_float4(c0.x + bias.x, c0.y + bias.y,
                                    c1.x + bias.z, c1.y + bias.w);
            *reinterpret_cast<float4*>(out + (size_t)orow * H_DIM + n) = v;
        }
    }
}

// ---------------------------------------------------------------------------
extern "C" void kernel_launch(void* const* d_in, const int* in_sizes, int n_in,
                              void* d_out, int out_size) {
    // Bind inputs by element count (robust to metadata ordering):
    //   inputs  : 2048*512      = 1048576 f32
    //   idx     : 2048          (int32 or int64 — handled on device)
    //   weights : 16*512*512    = 4194304 f32
    //   biases  : 16*512        = 8192 f32
    const float* X   = nullptr;
    const int*   idx = nullptr;
    const float* W   = nullptr;
    const float* B   = nullptr;
    for (int i = 0; i < n_in; i++) {
        switch (in_sizes[i]) {
            case 1048576: X   = (const float*)d_in[i]; break;
            case 2048:    idx = (const int*)d_in[i];   break;
            case 4194304: W   = (const float*)d_in[i]; break;
            case 8192:    B   = (const float*)d_in[i]; break;
        }
    }
    float* out = (float*)d_out;  // (2048, 512) f32

    bucket_kernel<<<1, 256>>>(idx);

    // worst case: all rows in one head -> ceil(2048/64) = 32 row tiles
    dim3 grid(H_DIM / BN, N_HEADS, N_ROWS / BM);
    multilinear_gemm<<<grid, 256>>>(X, W, B, out);
}